// round 5
// baseline (speedup 1.0000x reference)
#include <cuda_runtime.h>

// AntiAliasInterpolation2d: depthwise 13x13 Gaussian (pad 6) + bilinear x0.25,
// folded into an effective separable 14-tap kernel applied at stride 4.
// R4: vertical-first streaming conv with prefetch depth 2 (8 rows in flight per
// thread) to cover queued DRAM latency exposed in R3 (issue=20%, DRAM=46%).
// (R5 = R4 rerun: previous bench died to container infra failure, no data.)

#define IH 512
#define IW 512
#define NC 3
#define KS 13
#define OH 128
#define OW 128
#define TH 16                    // output rows per strip
#define IN_ROWS (4 * TH + 10)    // 74 input rows per strip
#define NT 128                   // threads per block (one float4 column each)
#define VB_W (OW + 4)            // vbuf width in float4 (2 zero pads each side)

__device__ float g_eh[NC][14];   // width factor (effective 14-tap)
__device__ float g_ev[NC][14];   // height factor

__global__ void build_factors_kernel(const float* __restrict__ w) {
    __shared__ float k2[NC][KS][KS];
    __shared__ float rowsum[NC][KS];
    __shared__ float colsum[NC][KS];
    int t = threadIdx.x;
    for (int i = t; i < NC * KS * KS; i += blockDim.x)
        ((float*)k2)[i] = w[i];
    __syncthreads();
    if (t < NC * KS) {
        int c = t / KS, i = t % KS;
        float rs = 0.f, cs = 0.f;
#pragma unroll
        for (int j = 0; j < KS; ++j) {
            rs += k2[c][i][j];   // sum over width  -> height factor
            cs += k2[c][j][i];   // sum over height -> width factor
        }
        rowsum[c][i] = rs;
        colsum[c][i] = cs;
    }
    __syncthreads();
    if (t < NC * 14) {
        int c = t / 14, u = t % 14;
        float va = (u < KS) ? rowsum[c][u] : 0.f;
        float vb = (u >= 1) ? rowsum[c][u - 1] : 0.f;
        g_ev[c][u] = 0.5f * (va + vb);
        float ha = (u < KS) ? colsum[c][u] : 0.f;
        float hb = (u >= 1) ? colsum[c][u - 1] : 0.f;
        g_eh[c][u] = 0.5f * (ha + hb);
    }
}

__device__ __forceinline__ void fma4(float4& a, const float4 v, const float w) {
    a.x += v.x * w; a.y += v.y * w; a.z += v.z * w; a.w += v.w * w;
}

__global__ __launch_bounds__(NT, 6) void aa_interp_kernel(
    const float* __restrict__ x, float* __restrict__ out) {
    const int strip = blockIdx.x;          // 16-row output strip (0..7)
    const int img   = blockIdx.y;          // n*C + c (0..95)
    const int c     = img % NC;
    const int i0    = strip * TH;
    const int t     = threadIdx.x;         // float4 column 0..127

    __shared__ float4 vbuf[TH][VB_W];      // vertically-reduced rows (33.8 KB)

    // zero side pads (2 float4 each side per row)
    if (t < TH) {
        const float4 z = make_float4(0.f, 0.f, 0.f, 0.f);
        vbuf[t][0] = z; vbuf[t][1] = z;
        vbuf[t][VB_W - 2] = z; vbuf[t][VB_W - 1] = z;
    }

    float ev[14];
#pragma unroll
    for (int v = 0; v < 14; ++v) ev[v] = g_ev[c][v];

    const float4* __restrict__ xin4 =
        (const float4*)x + (size_t)img * IH * (IW / 4);
    const int rbase = 4 * i0 - 5;

    const float4 z4 = make_float4(0.f, 0.f, 0.f, 0.f);
    float4 A0 = z4, A1 = z4, A2 = z4, A3 = z4;

    // u_ is a compile-time constant in the unrolled loop: u_<IN_ROWS folds away.
#define LDROW(u_) (((u_) < IN_ROWS && (unsigned)(rbase + (u_)) < (unsigned)IH) \
        ? __ldg(xin4 + (size_t)(rbase + (u_)) * (IW / 4) + t) : z4)

    // depth-2 software pipeline: batches b (compute), b+1 (n->...), b+2 (loading)
    float4 n0 = LDROW(0), n1 = LDROW(1), n2 = LDROW(2), n3 = LDROW(3);
    float4 m0 = LDROW(4), m1 = LDROW(5), m2 = LDROW(6), m3 = LDROW(7);
#pragma unroll
    for (int b = 0; b <= 18; ++b) {
        const float4 c0 = n0, c1 = n1, c2 = n2, c3 = n3;
        n0 = m0; n1 = m1; n2 = m2; n3 = m3;
        {
            const int u = 4 * b + 8;
            m0 = LDROW(u); m1 = LDROW(u + 1);
            m2 = LDROW(u + 2); m3 = LDROW(u + 3);
        }
        // row 4b+0: taps 0,4,8,12 -> outputs b, b-1, b-2, b-3
        fma4(A0, c0, ev[0]); fma4(A1, c0, ev[4]);
        fma4(A2, c0, ev[8]); fma4(A3, c0, ev[12]);
        // row 4b+1: taps 1,5,9,13
        fma4(A0, c1, ev[1]); fma4(A1, c1, ev[5]);
        fma4(A2, c1, ev[9]); fma4(A3, c1, ev[13]);
        if (b >= 3) vbuf[b - 3][t + 2] = A3;     // output row b-3 complete
        // row 4b+2: taps 2,6,10
        fma4(A0, c2, ev[2]); fma4(A1, c2, ev[6]); fma4(A2, c2, ev[10]);
        // row 4b+3: taps 3,7,11
        fma4(A0, c3, ev[3]); fma4(A1, c3, ev[7]); fma4(A2, c3, ev[11]);
        // rotate (renamed away by full unroll)
        A3 = A2; A2 = A1; A1 = A0; A0 = z4;
    }
#undef LDROW
    __syncthreads();

    // horizontal pass from smem: output col j = t, rows 0..15
    float eh[14];
#pragma unroll
    for (int v = 0; v < 14; ++v) eh[v] = g_eh[c][v];

    float* __restrict__ obase =
        out + (size_t)img * OH * OW + (size_t)i0 * OW + t;
#pragma unroll
    for (int i = 0; i < TH; ++i) {
        const float4 w0 = vbuf[i][t];
        const float4 w1 = vbuf[i][t + 1];
        const float4 w2 = vbuf[i][t + 2];
        const float4 w3 = vbuf[i][t + 3];
        const float4 w4 = vbuf[i][t + 4];
        const float win[20] = { w0.x, w0.y, w0.z, w0.w,
                                w1.x, w1.y, w1.z, w1.w,
                                w2.x, w2.y, w2.z, w2.w,
                                w3.x, w3.y, w3.z, w3.w,
                                w4.x, w4.y, w4.z, w4.w };
        float s = 0.f;
#pragma unroll
        for (int v = 0; v < 14; ++v) s += win[v + 3] * eh[v];
        obase[(size_t)i * OW] = s;
    }
}

extern "C" void kernel_launch(void* const* d_in, const int* in_sizes, int n_in,
                              void* d_out, int out_size) {
    const float* x = (const float*)d_in[0];
    const float* w = (const float*)d_in[1];
    float* out = (float*)d_out;

    const int nimg = in_sizes[0] / (IH * IW);   // 32*3 = 96

    build_factors_kernel<<<1, 128>>>(w);
    dim3 grid(OH / TH, nimg);
    aa_interp_kernel<<<grid, NT>>>(x, out);
}

// round 6
// speedup vs baseline: 1.1628x; 1.1628x over previous
#include <cuda_runtime.h>
#include <cstdint>

// AntiAliasInterpolation2d: depthwise 13x13 Gaussian (pad 6) + bilinear x0.25,
// folded into an effective separable 14-tap kernel applied at stride 4.
// R6: vertical conv consumes a per-thread cp.async smem ring (depth-3 groups,
// no barriers) -- MLP is decoupled from registers after R4/R5 showed ptxas
// collapses register prefetch under the occupancy reg budget.

#define IH 512
#define IW 512
#define NC 3
#define KS 13
#define OH 128
#define OW 128
#define TH 16                    // output rows per strip
#define IN_ROWS (4 * TH + 10)    // 74 input rows per strip
#define NT 128                   // threads per block (one float4 column each)
#define VB_W (OW + 4)            // vbuf width in float4 (2 zero pads each side)
#define RING 16                  // ring rows (4 batches resident)
#define SMEM_BYTES (RING * 128 * 16 + TH * VB_W * 16)   // 66560

__device__ float g_eh[NC][14];   // width factor (effective 14-tap)
__device__ float g_ev[NC][14];   // height factor

__global__ void build_factors_kernel(const float* __restrict__ w) {
    __shared__ float k2[NC][KS][KS];
    __shared__ float rowsum[NC][KS];
    __shared__ float colsum[NC][KS];
    int t = threadIdx.x;
    for (int i = t; i < NC * KS * KS; i += blockDim.x)
        ((float*)k2)[i] = w[i];
    __syncthreads();
    if (t < NC * KS) {
        int c = t / KS, i = t % KS;
        float rs = 0.f, cs = 0.f;
#pragma unroll
        for (int j = 0; j < KS; ++j) {
            rs += k2[c][i][j];   // sum over width  -> height factor
            cs += k2[c][j][i];   // sum over height -> width factor
        }
        rowsum[c][i] = rs;
        colsum[c][i] = cs;
    }
    __syncthreads();
    if (t < NC * 14) {
        int c = t / 14, u = t % 14;
        float va = (u < KS) ? rowsum[c][u] : 0.f;
        float vb = (u >= 1) ? rowsum[c][u - 1] : 0.f;
        g_ev[c][u] = 0.5f * (va + vb);
        float ha = (u < KS) ? colsum[c][u] : 0.f;
        float hb = (u >= 1) ? colsum[c][u - 1] : 0.f;
        g_eh[c][u] = 0.5f * (ha + hb);
    }
}

__device__ __forceinline__ void fma4(float4& a, const float4 v, const float w) {
    a.x += v.x * w; a.y += v.y * w; a.z += v.z * w; a.w += v.w * w;
}

__device__ __forceinline__ void cp16(float4* dst_smem, const float4* src, int sz) {
    uint32_t d = (uint32_t)__cvta_generic_to_shared(dst_smem);
    asm volatile("cp.async.cg.shared.global [%0], [%1], 16, %2;\n"
                 :: "r"(d), "l"(src), "r"(sz) : "memory");
}
#define CP_COMMIT() asm volatile("cp.async.commit_group;\n" ::: "memory")
#define CP_WAIT3()  asm volatile("cp.async.wait_group 3;\n" ::: "memory")

__global__ __launch_bounds__(NT, 3) void aa_interp_kernel(
    const float* __restrict__ x, float* __restrict__ out) {
    extern __shared__ float4 smem_dyn[];
    float4 (*ring)[128]  = (float4(*)[128])smem_dyn;              // 32 KB
    float4 (*vbuf)[VB_W] = (float4(*)[VB_W])(smem_dyn + RING * 128); // 33.8 KB

    const int strip = blockIdx.x;          // 16-row output strip (0..7)
    const int img   = blockIdx.y;          // n*C + c (0..95)
    const int c     = img % NC;
    const int i0    = strip * TH;
    const int t     = threadIdx.x;         // float4 column 0..127

    // zero side pads of vbuf (2 float4 each side per row)
    if (t < TH) {
        const float4 z = make_float4(0.f, 0.f, 0.f, 0.f);
        vbuf[t][0] = z; vbuf[t][1] = z;
        vbuf[t][VB_W - 2] = z; vbuf[t][VB_W - 1] = z;
    }

    float ev[14];
#pragma unroll
    for (int v = 0; v < 14; ++v) ev[v] = g_ev[c][v];

    const float4* __restrict__ xin4 =
        (const float4*)x + (size_t)img * IH * (IW / 4);
    const int rbase = 4 * i0 - 5;

    // issue one 4-row batch q (rows 4q..4q+3) into the ring; OOB -> zero-fill
#define ISSUE(q_) do {                                                        \
        _Pragma("unroll")                                                     \
        for (int k_ = 0; k_ < 4; ++k_) {                                      \
            const int u_ = 4 * (q_) + k_;                                     \
            const int r_ = rbase + u_;                                        \
            const bool ok_ = (u_ < IN_ROWS) && ((unsigned)r_ < (unsigned)IH); \
            const int rc_ = ok_ ? r_ : 0;                                     \
            cp16(&ring[(4 * (q_) + k_) & (RING - 1)][t],                      \
                 xin4 + (size_t)rc_ * (IW / 4) + t, ok_ ? 16 : 0);            \
        }                                                                     \
        CP_COMMIT();                                                          \
    } while (0)

    // prologue: batches 0..2 in flight
    ISSUE(0); ISSUE(1); ISSUE(2);

    const float4 z4 = make_float4(0.f, 0.f, 0.f, 0.f);
    float4 A0 = z4, A1 = z4, A2 = z4, A3 = z4;

#pragma unroll
    for (int b = 0; b <= 18; ++b) {
        // keep depth-3: issue batch b+3 (or an empty group past the end)
        if (b + 3 <= 18) { ISSUE(b + 3); } else { CP_COMMIT(); }
        CP_WAIT3();                         // batch b is now complete
        const int s = (4 * b) & (RING - 1);
        const float4 c0 = ring[s + 0][t];
        const float4 c1 = ring[s + 1][t];
        const float4 c2 = ring[s + 2][t];
        const float4 c3 = ring[s + 3][t];
        // row 4b+0: taps 0,4,8,12 -> outputs b, b-1, b-2, b-3
        fma4(A0, c0, ev[0]); fma4(A1, c0, ev[4]);
        fma4(A2, c0, ev[8]); fma4(A3, c0, ev[12]);
        // row 4b+1: taps 1,5,9,13
        fma4(A0, c1, ev[1]); fma4(A1, c1, ev[5]);
        fma4(A2, c1, ev[9]); fma4(A3, c1, ev[13]);
        if (b >= 3) vbuf[b - 3][t + 2] = A3;     // output row b-3 complete
        // row 4b+2: taps 2,6,10
        fma4(A0, c2, ev[2]); fma4(A1, c2, ev[6]); fma4(A2, c2, ev[10]);
        // row 4b+3: taps 3,7,11
        fma4(A0, c3, ev[3]); fma4(A1, c3, ev[7]); fma4(A2, c3, ev[11]);
        // rotate (renamed away by full unroll)
        A3 = A2; A2 = A1; A1 = A0; A0 = z4;
    }
#undef ISSUE
    __syncthreads();

    // horizontal pass from smem: output col j = t, rows 0..15
    float eh[14];
#pragma unroll
    for (int v = 0; v < 14; ++v) eh[v] = g_eh[c][v];

    float* __restrict__ obase =
        out + (size_t)img * OH * OW + (size_t)i0 * OW + t;
#pragma unroll
    for (int i = 0; i < TH; ++i) {
        const float4 w0 = vbuf[i][t];
        const float4 w1 = vbuf[i][t + 1];
        const float4 w2 = vbuf[i][t + 2];
        const float4 w3 = vbuf[i][t + 3];
        const float4 w4 = vbuf[i][t + 4];
        const float win[20] = { w0.x, w0.y, w0.z, w0.w,
                                w1.x, w1.y, w1.z, w1.w,
                                w2.x, w2.y, w2.z, w2.w,
                                w3.x, w3.y, w3.z, w3.w,
                                w4.x, w4.y, w4.z, w4.w };
        float s = 0.f;
#pragma unroll
        for (int v = 0; v < 14; ++v) s += win[v + 3] * eh[v];
        obase[(size_t)i * OW] = s;
    }
}

extern "C" void kernel_launch(void* const* d_in, const int* in_sizes, int n_in,
                              void* d_out, int out_size) {
    const float* x = (const float*)d_in[0];
    const float* w = (const float*)d_in[1];
    float* out = (float*)d_out;

    const int nimg = in_sizes[0] / (IH * IW);   // 32*3 = 96

    static bool attr_set = false;
    if (!attr_set) {
        cudaFuncSetAttribute(aa_interp_kernel,
                             cudaFuncAttributeMaxDynamicSharedMemorySize,
                             SMEM_BYTES);
        attr_set = true;
    }

    build_factors_kernel<<<1, 128>>>(w);
    dim3 grid(OH / TH, nimg);
    aa_interp_kernel<<<grid, NT, SMEM_BYTES>>>(x, out);
}

// round 7
// speedup vs baseline: 1.2425x; 1.0685x over previous
#include <cuda_runtime.h>
#include <cstdint>

// AntiAliasInterpolation2d: depthwise 13x13 Gaussian (pad 6) + bilinear x0.25,
// folded into an effective separable 14-tap kernel applied at stride 4.
// R7: fully fused single-phase streaming. cp.async 12-row ring (depth-2 groups,
// intra-thread consistency, no barriers) feeds the vertical conv; completed rows
// drop into a 6-row vbuf ring and are horizontally convolved every 2 rows.
// smem 37.2KB -> 6 blocks/SM -> 768 blocks = one full wave (no tail).

#define IH 512
#define IW 512
#define NC 3
#define KS 13
#define OH 128
#define OW 128
#define TH 16                    // output rows per strip
#define IN_ROWS (4 * TH + 10)    // 74 input rows per strip
#define NT 128                   // threads per block (one float4 column each)
#define VB_W (OW + 4)            // vbuf width in float4 (2 zero pads each side)
#define RING 12                  // cp.async ring rows (3 batches resident)
#define VR 6                     // vbuf ring rows

__device__ float g_eh[NC][14];   // width factor (effective 14-tap)
__device__ float g_ev[NC][14];   // height factor

__global__ void build_factors_kernel(const float* __restrict__ w) {
    __shared__ float k2[NC][KS][KS];
    __shared__ float rowsum[NC][KS];
    __shared__ float colsum[NC][KS];
    int t = threadIdx.x;
    for (int i = t; i < NC * KS * KS; i += blockDim.x)
        ((float*)k2)[i] = w[i];
    __syncthreads();
    if (t < NC * KS) {
        int c = t / KS, i = t % KS;
        float rs = 0.f, cs = 0.f;
#pragma unroll
        for (int j = 0; j < KS; ++j) {
            rs += k2[c][i][j];   // sum over width  -> height factor
            cs += k2[c][j][i];   // sum over height -> width factor
        }
        rowsum[c][i] = rs;
        colsum[c][i] = cs;
    }
    __syncthreads();
    if (t < NC * 14) {
        int c = t / 14, u = t % 14;
        float va = (u < KS) ? rowsum[c][u] : 0.f;
        float vb = (u >= 1) ? rowsum[c][u - 1] : 0.f;
        g_ev[c][u] = 0.5f * (va + vb);
        float ha = (u < KS) ? colsum[c][u] : 0.f;
        float hb = (u >= 1) ? colsum[c][u - 1] : 0.f;
        g_eh[c][u] = 0.5f * (ha + hb);
    }
}

__device__ __forceinline__ void fma4(float4& a, const float4 v, const float w) {
    a.x += v.x * w; a.y += v.y * w; a.z += v.z * w; a.w += v.w * w;
}

__device__ __forceinline__ void cp16(float4* dst_smem, const float4* src, int sz) {
    uint32_t d = (uint32_t)__cvta_generic_to_shared(dst_smem);
    asm volatile("cp.async.cg.shared.global [%0], [%1], 16, %2;\n"
                 :: "r"(d), "l"(src), "r"(sz) : "memory");
}
#define CP_COMMIT() asm volatile("cp.async.commit_group;\n" ::: "memory")
#define CP_WAIT2()  asm volatile("cp.async.wait_group 2;\n" ::: "memory")

__global__ __launch_bounds__(NT, 6) void aa_interp_kernel(
    const float* __restrict__ x, float* __restrict__ out) {
    __shared__ float4 ring[RING][128];     // 24.6 KB staging
    __shared__ float4 vbuf[VR][VB_W];      // 12.7 KB vertically-reduced rows

    const int strip = blockIdx.x;          // 16-row output strip (0..7)
    const int img   = blockIdx.y;          // n*C + c (0..95)
    const int c     = img % NC;
    const int i0    = strip * TH;
    const int t     = threadIdx.x;         // float4 column 0..127

    // zero side pads of vbuf ring (2 float4 each side per slot)
    if (t < VR) {
        const float4 z = make_float4(0.f, 0.f, 0.f, 0.f);
        vbuf[t][0] = z; vbuf[t][1] = z;
        vbuf[t][VB_W - 2] = z; vbuf[t][VB_W - 1] = z;
    }

    float ev[14], eh[14];
#pragma unroll
    for (int v = 0; v < 14; ++v) { ev[v] = g_ev[c][v]; eh[v] = g_eh[c][v]; }

    const float4* __restrict__ xin4 =
        (const float4*)x + (size_t)img * IH * (IW / 4);
    const int rbase = 4 * i0 - 5;

    // issue one 4-row batch q (rows 4q..4q+3) into the ring; OOB -> zero-fill
#define ISSUE(q_) do {                                                        \
        _Pragma("unroll")                                                     \
        for (int k_ = 0; k_ < 4; ++k_) {                                      \
            const int u_ = 4 * (q_) + k_;                                     \
            const int r_ = rbase + u_;                                        \
            const bool ok_ = (u_ < IN_ROWS) && ((unsigned)r_ < (unsigned)IH); \
            const int rc_ = ok_ ? r_ : 0;                                     \
            cp16(&ring[u_ % RING][t],                                         \
                 xin4 + (size_t)rc_ * (IW / 4) + t, ok_ ? 16 : 0);            \
        }                                                                     \
        CP_COMMIT();                                                          \
    } while (0)

    // prologue: batches 0..1 in flight
    ISSUE(0); ISSUE(1);

    const float4 z4 = make_float4(0.f, 0.f, 0.f, 0.f);
    float4 A0 = z4, A1 = z4, A2 = z4, A3 = z4;

    float* __restrict__ obase = out + (size_t)img * OH * OW + (size_t)i0 * OW + t;

#pragma unroll
    for (int b = 0; b <= 18; ++b) {
        // keep depth: issue batch b+2 (or an empty group past the end)
        if (b + 2 <= 18) { ISSUE(b + 2); } else { CP_COMMIT(); }
        CP_WAIT2();                         // batch b is now complete
        const int s = (4 * b) % RING;       // compile-time in unrolled loop
        const float4 c0 = ring[s + 0][t];
        const float4 c1 = ring[s + 1][t];
        const float4 c2 = ring[s + 2][t];
        const float4 c3 = ring[s + 3][t];
        // row 4b+0: taps 0,4,8,12 -> outputs b, b-1, b-2, b-3
        fma4(A0, c0, ev[0]); fma4(A1, c0, ev[4]);
        fma4(A2, c0, ev[8]); fma4(A3, c0, ev[12]);
        // row 4b+1: taps 1,5,9,13
        fma4(A0, c1, ev[1]); fma4(A1, c1, ev[5]);
        fma4(A2, c1, ev[9]); fma4(A3, c1, ev[13]);
        if (b >= 3) vbuf[(b - 3) % VR][t + 2] = A3;   // output row b-3 complete
        // row 4b+2: taps 2,6,10
        fma4(A0, c2, ev[2]); fma4(A1, c2, ev[6]); fma4(A2, c2, ev[10]);
        // row 4b+3: taps 3,7,11
        fma4(A0, c3, ev[3]); fma4(A1, c3, ev[7]); fma4(A2, c3, ev[11]);
        // rotate (renamed away by full unroll)
        A3 = A2; A2 = A1; A1 = A0; A0 = z4;

        // every 2 completed rows: horizontal conv + store (rows b-4, b-3)
        if (b >= 4 && ((b - 3) & 1)) {
            __syncthreads();
#pragma unroll
            for (int rr = b - 4; rr <= b - 3; ++rr) {
                const int sl = rr % VR;     // compile-time
                const float4 w0 = vbuf[sl][t];
                const float4 w1 = vbuf[sl][t + 1];
                const float4 w2 = vbuf[sl][t + 2];
                const float4 w3 = vbuf[sl][t + 3];
                const float4 w4 = vbuf[sl][t + 4];
                const float win[20] = { w0.x, w0.y, w0.z, w0.w,
                                        w1.x, w1.y, w1.z, w1.w,
                                        w2.x, w2.y, w2.z, w2.w,
                                        w3.x, w3.y, w3.z, w3.w,
                                        w4.x, w4.y, w4.z, w4.w };
                float s2 = 0.f;
#pragma unroll
                for (int v = 0; v < 14; ++v) s2 += win[v + 3] * eh[v];
                obase[(size_t)rr * OW] = s2;
            }
        }
    }
#undef ISSUE
}

extern "C" void kernel_launch(void* const* d_in, const int* in_sizes, int n_in,
                              void* d_out, int out_size) {
    const float* x = (const float*)d_in[0];
    const float* w = (const float*)d_in[1];
    float* out = (float*)d_out;

    const int nimg = in_sizes[0] / (IH * IW);   // 32*3 = 96

    build_factors_kernel<<<1, 128>>>(w);
    dim3 grid(OH / TH, nimg);
    aa_interp_kernel<<<grid, NT>>>(x, out);
}